// round 5
// baseline (speedup 1.0000x reference)
#include <cuda_runtime.h>
#include <cstdint>

#define N_USERS 100000
#define N_ITEMS 200000
#define N_NODES (N_USERS + N_ITEMS)
#define EMB 64
#define N_HOPS 3
#define NNZ 2000000
#define CAP 32                             // max edges per row (deg ~ Poisson(6.7))
#define ROW_STRIDE (N_HOPS * EMB)          // 192 floats per node in output
#define FLAT ((size_t)N_NODES * EMB)       // 19,200,000
#define MASK_BYTES (FLAT / 8)              // 2,400,000 bytes per hop

#define BUILD_BLOCKS ((NNZ + 255) / 256)           // 7813
#define HOP_BLOCKS   ((N_NODES * 16) / 256)        // 18750
#define MASK_BLOCKS  ((unsigned)(MASK_BYTES / 256))// 9375

// Padded-CSR scratch: per row up to CAP slots of {veff_h0, veff_h1, veff_h2, col}.
__device__ float4  g_slot[(size_t)N_NODES * CAP];   // 153.6 MB
__device__ int     g_cnt[N_NODES];
__device__ uint8_t g_mask[N_HOPS][MASK_BYTES];      // packed mdrop keep-bits

__host__ __device__ __forceinline__ uint32_t rotl32(uint32_t x, int r) {
    return (x << r) | (x >> (32 - r));
}

// Threefry-2x32, 20 rounds, exactly as jax._src.prng.threefry2x32.
__host__ __device__ __forceinline__ void threefry2x32(
    uint32_t k0, uint32_t k1, uint32_t c0, uint32_t c1,
    uint32_t& o0, uint32_t& o1)
{
    uint32_t ks2 = k0 ^ k1 ^ 0x1BD11BDAu;
    uint32_t x0 = c0 + k0;
    uint32_t x1 = c1 + k1;
#define TF_ROUND(r) { x0 += x1; x1 = rotl32(x1, (r)); x1 ^= x0; }
    TF_ROUND(13) TF_ROUND(15) TF_ROUND(26) TF_ROUND(6)
    x0 += k1;  x1 += ks2 + 1u;
    TF_ROUND(17) TF_ROUND(29) TF_ROUND(16) TF_ROUND(24)
    x0 += ks2; x1 += k0 + 2u;
    TF_ROUND(13) TF_ROUND(15) TF_ROUND(26) TF_ROUND(6)
    x0 += k0;  x1 += k1 + 3u;
    TF_ROUND(17) TF_ROUND(29) TF_ROUND(16) TF_ROUND(24)
    x0 += k1;  x1 += ks2 + 4u;
    TF_ROUND(13) TF_ROUND(15) TF_ROUND(26) TF_ROUND(6)
    x0 += ks2; x1 += k0 + 5u;
#undef TF_ROUND
    o0 = x0;
    o1 = x1;
}

// jax threefry_partitionable=True, bit_width=32:
// bits[i] = w0 ^ w1 of threefry(key, (hi32(i)=0, lo32(i)=i))
__device__ __forceinline__ uint32_t tf_bits32(uint32_t k0, uint32_t k1, uint32_t i) {
    uint32_t o0, o1;
    threefry2x32(k0, k1, 0u, i, o0, o1);
    return o0 ^ o1;
}

// Message-dropout mask generation: one byte (8 elements) per thread.
// keep = u >= 0.1f  <=>  (bits >> 9) >= 0xCCCCD  (exact on the k*2^-23 grid)
__device__ __forceinline__ void do_mask(unsigned mblk, int hop,
                                        uint32_t k0, uint32_t k1)
{
    unsigned t = mblk * 256u + threadIdx.x;     // byte index
    uint32_t base = t * 8u;
    uint32_t byte = 0;
#pragma unroll
    for (int i = 0; i < 8; i++) {
        uint32_t b = tf_bits32(k0, k1, base + (uint32_t)i);
        byte |= (((b >> 9) >= 0xCCCCDu) ? 1u : 0u) << i;
    }
    g_mask[hop][t] = (uint8_t)byte;
}

// Launch 1: build padded CSR (+ all-hop edge dropout) in blocks [0, BUILD_BLOCKS),
// and generate hop-0 mdrop mask in the remaining blocks.
// edge keep = floor(0.5 + u) > 0  <=>  u >= 0.5  <=>  top bit of bits set.
__global__ void __launch_bounds__(256)
build_kernel(const float* __restrict__ vals,
             const int* __restrict__ rows,
             const int* __restrict__ cols,
             uint32_t e0k0, uint32_t e0k1,
             uint32_t e1k0, uint32_t e1k1,
             uint32_t e2k0, uint32_t e2k1,
             uint32_t m0k0, uint32_t m0k1)
{
    if (blockIdx.x >= BUILD_BLOCKS) {
        do_mask(blockIdx.x - BUILD_BLOCKS, 0, m0k0, m0k1);
        return;
    }
    unsigned e = blockIdx.x * 256u + threadIdx.x;
    if (e >= NNZ) return;
    int r = rows[e];
    int c = cols[e];
    float v2 = vals[e] * 2.0f;            // 1/(1-0.5) rescale
    int slot = atomicAdd(&g_cnt[r], 1);
    if (slot < CAP) {
        float4 sd;
        sd.x = (tf_bits32(e0k0, e0k1, e) & 0x80000000u) ? v2 : 0.0f;
        sd.y = (tf_bits32(e1k0, e1k1, e) & 0x80000000u) ? v2 : 0.0f;
        sd.z = (tf_bits32(e2k0, e2k1, e) & 0x80000000u) ? v2 : 0.0f;
        sd.w = __int_as_float(c);
        g_slot[(size_t)r * CAP + slot] = sd;
    }
}

// Launches 2-4: fused SpMM + mask-apply for hop HOP in blocks [0, HOP_BLOCKS),
// plus (if NEXT_MASK) mdrop-mask generation for hop HOP+1 in the rest.
template <int HOP, bool NEXT_MASK>
__global__ void __launch_bounds__(256)
hop_kernel(const float* __restrict__ user_e,
           const float* __restrict__ item_e,
           float* __restrict__ out,
           uint32_t nk0, uint32_t nk1)
{
    if (NEXT_MASK && blockIdx.x >= HOP_BLOCKS) {
        do_mask(blockIdx.x - HOP_BLOCKS, HOP + 1, nk0, nk1);
        return;
    }
    unsigned t = blockIdx.x * 256u + threadIdx.x;
    unsigned r = t >> 4;                  // row = half-warp id
    int hl = t & 15;

    int deg = g_cnt[r];
    if (deg > CAP) deg = CAP;
    const float4* sbase = g_slot + (size_t)r * CAP;

    auto src_row = [&](int c) -> const float4* {
        if (HOP == 0) {
            return (c < N_USERS)
                ? (const float4*)(user_e + (size_t)c * EMB)
                : (const float4*)(item_e + (size_t)(c - N_USERS) * EMB);
        } else {
            return (const float4*)(out + (size_t)c * ROW_STRIDE + (size_t)(HOP - 1) * EMB);
        }
    };

    float4 a0 = make_float4(0.f, 0.f, 0.f, 0.f);
    float4 a1 = make_float4(0.f, 0.f, 0.f, 0.f);
    float4 a2 = make_float4(0.f, 0.f, 0.f, 0.f);
    float4 a3 = make_float4(0.f, 0.f, 0.f, 0.f);

#define PICKV(sd) ((HOP == 0) ? (sd).x : (HOP == 1) ? (sd).y : (sd).z)
#define GATHER(sd, acc)                                            \
    {                                                              \
        float vj = PICKV(sd);                                      \
        if (vj != 0.0f) {                                          \
            float4 s = __ldg(src_row(__float_as_int((sd).w)) + hl);\
            acc.x += vj * s.x; acc.y += vj * s.y;                  \
            acc.z += vj * s.z; acc.w += vj * s.w;                  \
        }                                                          \
    }

    int j = 0;
    for (; j + 4 <= deg; j += 4) {
        float4 sd0 = __ldg(&sbase[j + 0]);
        float4 sd1 = __ldg(&sbase[j + 1]);
        float4 sd2 = __ldg(&sbase[j + 2]);
        float4 sd3 = __ldg(&sbase[j + 3]);
        GATHER(sd0, a0) GATHER(sd1, a1) GATHER(sd2, a2) GATHER(sd3, a3)
    }
    if (j + 2 <= deg) {
        float4 sd0 = __ldg(&sbase[j + 0]);
        float4 sd1 = __ldg(&sbase[j + 1]);
        GATHER(sd0, a0) GATHER(sd1, a1)
        j += 2;
    }
    if (j < deg) {
        float4 sd0 = __ldg(&sbase[j]);
        GATHER(sd0, a2)
    }
#undef GATHER
#undef PICKV

    float4 acc;
    acc.x = (a0.x + a1.x) + (a2.x + a3.x);
    acc.y = (a0.y + a1.y) + (a2.y + a3.y);
    acc.z = (a0.z + a1.z) + (a2.z + a3.z);
    acc.w = (a0.w + a1.w) + (a2.w + a3.w);

    // Apply precomputed message-dropout mask (bit per element).
    const float MSCALE = (float)(1.0 / (1.0 - 0.1));
    uint8_t mbyte = g_mask[HOP][r * 8u + (unsigned)(hl >> 1)];
    int sh = (hl & 1) * 4;
    acc.x = ((mbyte >> (sh + 0)) & 1) ? acc.x * MSCALE : 0.0f;
    acc.y = ((mbyte >> (sh + 1)) & 1) ? acc.y * MSCALE : 0.0f;
    acc.z = ((mbyte >> (sh + 2)) & 1) ? acc.z * MSCALE : 0.0f;
    acc.w = ((mbyte >> (sh + 3)) & 1) ? acc.w * MSCALE : 0.0f;

    float4* dst = (float4*)(out + (size_t)r * ROW_STRIDE + (size_t)HOP * EMB) + hl;
    *dst = acc;
}

extern "C" void kernel_launch(void* const* d_in, const int* in_sizes, int n_in,
                              void* d_out, int out_size)
{
    const float* user_e = (const float*)d_in[0];
    const float* item_e = (const float*)d_in[1];
    const float* vals   = (const float*)d_in[2];
    const int*   rows   = (const int*)d_in[3];
    const int*   cols   = (const int*)d_in[4];
    float* out = (float*)d_out;

    // drop_key = jax.random.key(42) -> (0, 42); subkey_h = threefry(key, (0, h_data))
    uint32_t ek[3][2], mk[3][2];
    for (int h = 0; h < 3; h++) {
        threefry2x32(0u, 42u, 0u, (uint32_t)(2 * h),     ek[h][0], ek[h][1]);
        threefry2x32(0u, 42u, 0u, (uint32_t)(2 * h + 1), mk[h][0], mk[h][1]);
    }

    // Zero the per-row counters (graph-capturable async memset, no allocation)
    void* cnt_ptr = nullptr;
    cudaGetSymbolAddress(&cnt_ptr, g_cnt);
    cudaMemsetAsync(cnt_ptr, 0, sizeof(int) * N_NODES, 0);

    build_kernel<<<BUILD_BLOCKS + MASK_BLOCKS, 256>>>(
        vals, rows, cols,
        ek[0][0], ek[0][1], ek[1][0], ek[1][1], ek[2][0], ek[2][1],
        mk[0][0], mk[0][1]);

    hop_kernel<0, true ><<<HOP_BLOCKS + MASK_BLOCKS, 256>>>(user_e, item_e, out, mk[1][0], mk[1][1]);
    hop_kernel<1, true ><<<HOP_BLOCKS + MASK_BLOCKS, 256>>>(user_e, item_e, out, mk[2][0], mk[2][1]);
    hop_kernel<2, false><<<HOP_BLOCKS, 256>>>(user_e, item_e, out, 0u, 0u);
}

// round 6
// speedup vs baseline: 1.0861x; 1.0861x over previous
#include <cuda_runtime.h>
#include <cstdint>

#define N_USERS 100000
#define N_ITEMS 200000
#define N_NODES (N_USERS + N_ITEMS)
#define EMB 64
#define N_HOPS 3
#define NNZ 2000000
#define CAPK 24                            // max KEPT edges per row per hop (lambda ~3.35)
#define ROW_STRIDE (N_HOPS * EMB)          // 192 floats per node in output

#define BUILD_BLOCKS ((NNZ + 255) / 256)
#define HOP_BLOCKS   ((N_NODES * 16) / 256)

// Per-hop compact kept-edge lists: {v (f32 bits), col} per record.
__device__ int2 g_edge[N_HOPS][(size_t)N_NODES * CAPK];   // 3 * 57.6 MB
__device__ int  g_kcnt[N_HOPS][N_NODES];

__host__ __device__ __forceinline__ uint32_t rotl32(uint32_t x, int r) {
    return (x << r) | (x >> (32 - r));
}

// Threefry-2x32, 20 rounds, exactly as jax._src.prng.threefry2x32.
__host__ __device__ __forceinline__ void threefry2x32(
    uint32_t k0, uint32_t k1, uint32_t c0, uint32_t c1,
    uint32_t& o0, uint32_t& o1)
{
    uint32_t ks2 = k0 ^ k1 ^ 0x1BD11BDAu;
    uint32_t x0 = c0 + k0;
    uint32_t x1 = c1 + k1;
#define TF_ROUND(r) { x0 += x1; x1 = rotl32(x1, (r)); x1 ^= x0; }
    TF_ROUND(13) TF_ROUND(15) TF_ROUND(26) TF_ROUND(6)
    x0 += k1;  x1 += ks2 + 1u;
    TF_ROUND(17) TF_ROUND(29) TF_ROUND(16) TF_ROUND(24)
    x0 += ks2; x1 += k0 + 2u;
    TF_ROUND(13) TF_ROUND(15) TF_ROUND(26) TF_ROUND(6)
    x0 += k0;  x1 += k1 + 3u;
    TF_ROUND(17) TF_ROUND(29) TF_ROUND(16) TF_ROUND(24)
    x0 += k1;  x1 += ks2 + 4u;
    TF_ROUND(13) TF_ROUND(15) TF_ROUND(26) TF_ROUND(6)
    x0 += ks2; x1 += k0 + 5u;
#undef TF_ROUND
    o0 = x0;
    o1 = x1;
}

// jax threefry_partitionable=True, bit_width=32:
// bits[i] = w0 ^ w1 of threefry(key, (hi32(i)=0, lo32(i)=i))
__device__ __forceinline__ uint32_t tf_bits32(uint32_t k0, uint32_t k1, uint32_t i) {
    uint32_t o0, o1;
    threefry2x32(k0, k1, 0u, i, o0, o1);
    return o0 ^ o1;
}

// Build per-hop compact kept-edge lists in one pass over the COO edges.
// edge keep = floor(0.5 + u) > 0  <=>  u >= 0.5  <=>  top bit of bits set.
__global__ void __launch_bounds__(256)
build_kernel(const float* __restrict__ vals,
             const int* __restrict__ rows,
             const int* __restrict__ cols,
             uint32_t e0k0, uint32_t e0k1,
             uint32_t e1k0, uint32_t e1k1,
             uint32_t e2k0, uint32_t e2k1)
{
    unsigned e = blockIdx.x * 256u + threadIdx.x;
    if (e >= NNZ) return;
    int r = rows[e];
    int c = cols[e];
    float v2 = vals[e] * 2.0f;            // 1/(1-0.5) rescale
    int2 rec = make_int2(__float_as_int(v2), c);

    uint32_t ka[3][2] = {{e0k0, e0k1}, {e1k0, e1k1}, {e2k0, e2k1}};
#pragma unroll
    for (int h = 0; h < 3; h++) {
        uint32_t b = tf_bits32(ka[h][0], ka[h][1], e);
        if (b & 0x80000000u) {
            int slot = atomicAdd(&g_kcnt[h][r], 1);
            if (slot < CAPK)
                g_edge[h][(size_t)r * CAPK + slot] = rec;
        }
    }
}

// Fused SpMM + message dropout. One half-warp (16 lanes) per output row.
// Lane i holds edge record i; values broadcast by shfl so all gathers are
// issued with MLP = deg.
// mdrop keep = u >= 0.1f  <=>  (bits >> 9) >= 0xCCCCD  (exact on k*2^-23 grid)
template <int HOP>
__global__ void __launch_bounds__(256)
hop_kernel(const float* __restrict__ user_e,
           const float* __restrict__ item_e,
           float* __restrict__ out,
           uint32_t mk0, uint32_t mk1)
{
    unsigned t = blockIdx.x * 256u + threadIdx.x;
    unsigned r = t >> 4;                  // row = half-warp id
    int hl = t & 15;

    int deg = g_kcnt[HOP][r];
    if (deg > CAPK) deg = CAPK;
    const int2* ebase = g_edge[HOP] + (size_t)r * CAPK;

    float4 acc = make_float4(0.f, 0.f, 0.f, 0.f);

    for (int base = 0; base < deg; base += 16) {
        int n = deg - base;
        if (n > 16) n = 16;
        int2 rec = make_int2(0, 0);
        if (hl < n) rec = __ldg(&ebase[base + hl]);
        float myv = __int_as_float(rec.x);
        int myc = rec.y;

        for (int j = 0; j < n; j++) {
            float v = __shfl_sync(0xffffffffu, myv, j, 16);
            int   c = __shfl_sync(0xffffffffu, myc, j, 16);
            const float4* src;
            if (HOP == 0) {
                src = (c < N_USERS)
                    ? (const float4*)(user_e + (size_t)c * EMB)
                    : (const float4*)(item_e + (size_t)(c - N_USERS) * EMB);
            } else {
                src = (const float4*)(out + (size_t)c * ROW_STRIDE + (size_t)(HOP - 1) * EMB);
            }
            float4 s = __ldg(src + hl);
            acc.x += v * s.x; acc.y += v * s.y;
            acc.z += v * s.z; acc.w += v * s.w;
        }
    }

    // Fused message dropout (threefry hidden under gather latency).
    const float MSCALE = (float)(1.0 / (1.0 - 0.1));
    const uint32_t THRESH = 0xCCCCDu;
    uint32_t f = r * 64u + (uint32_t)hl * 4u;
    uint32_t b0 = tf_bits32(mk0, mk1, f + 0u);
    uint32_t b1 = tf_bits32(mk0, mk1, f + 1u);
    uint32_t b2 = tf_bits32(mk0, mk1, f + 2u);
    uint32_t b3 = tf_bits32(mk0, mk1, f + 3u);
    acc.x = ((b0 >> 9) >= THRESH) ? acc.x * MSCALE : 0.0f;
    acc.y = ((b1 >> 9) >= THRESH) ? acc.y * MSCALE : 0.0f;
    acc.z = ((b2 >> 9) >= THRESH) ? acc.z * MSCALE : 0.0f;
    acc.w = ((b3 >> 9) >= THRESH) ? acc.w * MSCALE : 0.0f;

    float4* dst = (float4*)(out + (size_t)r * ROW_STRIDE + (size_t)HOP * EMB) + hl;
    *dst = acc;
}

extern "C" void kernel_launch(void* const* d_in, const int* in_sizes, int n_in,
                              void* d_out, int out_size)
{
    const float* user_e = (const float*)d_in[0];
    const float* item_e = (const float*)d_in[1];
    const float* vals   = (const float*)d_in[2];
    const int*   rows   = (const int*)d_in[3];
    const int*   cols   = (const int*)d_in[4];
    float* out = (float*)d_out;

    // drop_key = jax.random.key(42) -> (0, 42); subkey_h = threefry(key, (0, h_data))
    uint32_t ek[3][2], mk[3][2];
    for (int h = 0; h < 3; h++) {
        threefry2x32(0u, 42u, 0u, (uint32_t)(2 * h),     ek[h][0], ek[h][1]);
        threefry2x32(0u, 42u, 0u, (uint32_t)(2 * h + 1), mk[h][0], mk[h][1]);
    }

    // Zero the per-hop per-row counters (graph-capturable, no allocation)
    void* cnt_ptr = nullptr;
    cudaGetSymbolAddress(&cnt_ptr, g_kcnt);
    cudaMemsetAsync(cnt_ptr, 0, sizeof(int) * N_HOPS * N_NODES, 0);

    build_kernel<<<BUILD_BLOCKS, 256>>>(
        vals, rows, cols,
        ek[0][0], ek[0][1], ek[1][0], ek[1][1], ek[2][0], ek[2][1]);

    hop_kernel<0><<<HOP_BLOCKS, 256>>>(user_e, item_e, out, mk[0][0], mk[0][1]);
    hop_kernel<1><<<HOP_BLOCKS, 256>>>(user_e, item_e, out, mk[1][0], mk[1][1]);
    hop_kernel<2><<<HOP_BLOCKS, 256>>>(user_e, item_e, out, mk[2][0], mk[2][1]);
}

// round 7
// speedup vs baseline: 1.2616x; 1.1615x over previous
#include <cuda_runtime.h>
#include <cstdint>

#define N_USERS 100000
#define N_ITEMS 200000
#define N_NODES (N_USERS + N_ITEMS)
#define EMB 64
#define N_HOPS 3
#define NNZ 2000000
#define CAPK 28                            // max KEPT edges per row per hop (lambda ~3.35)
#define ROW_STRIDE (N_HOPS * EMB)          // 192 floats per node in output

#define BUILD_BLOCKS ((NNZ + 255) / 256)
#define HOP_BLOCKS   ((N_NODES * 16) / 256)

// Per-hop compact kept-edge lists: {v (f32 bits), col} per record.
__device__ int2     g_edge[N_HOPS][(size_t)N_NODES * CAPK];  // 3 * 67 MB
__device__ uint32_t g_pcnt[N_NODES];       // 3 packed 10-bit per-hop counters

__host__ __device__ __forceinline__ uint32_t rotl32(uint32_t x, int r) {
    return (x << r) | (x >> (32 - r));
}

// Threefry-2x32, 20 rounds, exactly as jax._src.prng.threefry2x32.
__host__ __device__ __forceinline__ void threefry2x32(
    uint32_t k0, uint32_t k1, uint32_t c0, uint32_t c1,
    uint32_t& o0, uint32_t& o1)
{
    uint32_t ks2 = k0 ^ k1 ^ 0x1BD11BDAu;
    uint32_t x0 = c0 + k0;
    uint32_t x1 = c1 + k1;
#define TF_ROUND(r) { x0 += x1; x1 = rotl32(x1, (r)); x1 ^= x0; }
    TF_ROUND(13) TF_ROUND(15) TF_ROUND(26) TF_ROUND(6)
    x0 += k1;  x1 += ks2 + 1u;
    TF_ROUND(17) TF_ROUND(29) TF_ROUND(16) TF_ROUND(24)
    x0 += ks2; x1 += k0 + 2u;
    TF_ROUND(13) TF_ROUND(15) TF_ROUND(26) TF_ROUND(6)
    x0 += k0;  x1 += k1 + 3u;
    TF_ROUND(17) TF_ROUND(29) TF_ROUND(16) TF_ROUND(24)
    x0 += k1;  x1 += ks2 + 4u;
    TF_ROUND(13) TF_ROUND(15) TF_ROUND(26) TF_ROUND(6)
    x0 += ks2; x1 += k0 + 5u;
#undef TF_ROUND
    o0 = x0;
    o1 = x1;
}

// jax threefry_partitionable=True, bit_width=32:
// bits[i] = w0 ^ w1 of threefry(key, (hi32(i)=0, lo32(i)=i))
__device__ __forceinline__ uint32_t tf_bits32(uint32_t k0, uint32_t k1, uint32_t i) {
    uint32_t o0, o1;
    threefry2x32(k0, k1, 0u, i, o0, o1);
    return o0 ^ o1;
}

// Build per-hop compact kept-edge lists; ONE atomic per edge (packed counters).
// edge keep = floor(0.5 + u) > 0  <=>  u >= 0.5  <=>  top bit of bits set.
__global__ void __launch_bounds__(256)
build_kernel(const float* __restrict__ vals,
             const int* __restrict__ rows,
             const int* __restrict__ cols,
             uint32_t e0k0, uint32_t e0k1,
             uint32_t e1k0, uint32_t e1k1,
             uint32_t e2k0, uint32_t e2k1)
{
    unsigned e = blockIdx.x * 256u + threadIdx.x;
    if (e >= NNZ) return;
    int r = rows[e];
    int c = cols[e];
    float v2 = vals[e] * 2.0f;            // 1/(1-0.5) rescale
    int2 rec = make_int2(__float_as_int(v2), c);

    uint32_t keep0 = tf_bits32(e0k0, e0k1, e) >> 31;
    uint32_t keep1 = tf_bits32(e1k0, e1k1, e) >> 31;
    uint32_t keep2 = tf_bits32(e2k0, e2k1, e) >> 31;
    uint32_t add = keep0 | (keep1 << 10) | (keep2 << 20);
    if (add == 0) return;

    uint32_t old = atomicAdd(&g_pcnt[r], add);
    if (keep0) {
        uint32_t s = old & 0x3FFu;
        if (s < CAPK) g_edge[0][(size_t)r * CAPK + s] = rec;
    }
    if (keep1) {
        uint32_t s = (old >> 10) & 0x3FFu;
        if (s < CAPK) g_edge[1][(size_t)r * CAPK + s] = rec;
    }
    if (keep2) {
        uint32_t s = (old >> 20) & 0x3FFu;
        if (s < CAPK) g_edge[2][(size_t)r * CAPK + s] = rec;
    }
}

// Fused SpMM + message dropout. One half-warp (16 lanes) per output row.
// Records loaded as 8B broadcast __ldg; gathers unconditional (all edges kept).
// mdrop keep = u >= 0.1f  <=>  (bits >> 9) >= 0xCCCCD  (exact on k*2^-23 grid)
template <int HOP>
__global__ void __launch_bounds__(256)
hop_kernel(const float* __restrict__ user_e,
           const float* __restrict__ item_e,
           float* __restrict__ out,
           uint32_t mk0, uint32_t mk1)
{
    unsigned t = blockIdx.x * 256u + threadIdx.x;
    unsigned r = t >> 4;                  // row = half-warp id
    int hl = t & 15;

    int deg = (int)((g_pcnt[r] >> (10 * HOP)) & 0x3FFu);
    if (deg > CAPK) deg = CAPK;
    const int2* ebase = g_edge[HOP] + (size_t)r * CAPK;

    float4 a0 = make_float4(0.f, 0.f, 0.f, 0.f);
    float4 a1 = make_float4(0.f, 0.f, 0.f, 0.f);
    float4 a2 = make_float4(0.f, 0.f, 0.f, 0.f);
    float4 a3 = make_float4(0.f, 0.f, 0.f, 0.f);

    auto src_row = [&](int c) -> const float4* {
        if (HOP == 0) {
            return (c < N_USERS)
                ? (const float4*)(user_e + (size_t)c * EMB)
                : (const float4*)(item_e + (size_t)(c - N_USERS) * EMB);
        } else {
            return (const float4*)(out + (size_t)c * ROW_STRIDE + (size_t)(HOP - 1) * EMB);
        }
    };

#define GATHER(rec, acc)                                           \
    {                                                              \
        float vj = __int_as_float((rec).x);                        \
        float4 s = __ldg(src_row((rec).y) + hl);                   \
        acc.x += vj * s.x; acc.y += vj * s.y;                      \
        acc.z += vj * s.z; acc.w += vj * s.w;                      \
    }

    int j = 0;
    for (; j + 4 <= deg; j += 4) {
        int2 r0 = __ldg(&ebase[j + 0]);
        int2 r1 = __ldg(&ebase[j + 1]);
        int2 r2 = __ldg(&ebase[j + 2]);
        int2 r3 = __ldg(&ebase[j + 3]);
        GATHER(r0, a0) GATHER(r1, a1) GATHER(r2, a2) GATHER(r3, a3)
    }
    if (j + 2 <= deg) {
        int2 r0 = __ldg(&ebase[j + 0]);
        int2 r1 = __ldg(&ebase[j + 1]);
        GATHER(r0, a0) GATHER(r1, a1)
        j += 2;
    }
    if (j < deg) {
        int2 r0 = __ldg(&ebase[j]);
        GATHER(r0, a2)
    }
#undef GATHER

    float4 acc;
    acc.x = (a0.x + a1.x) + (a2.x + a3.x);
    acc.y = (a0.y + a1.y) + (a2.y + a3.y);
    acc.z = (a0.z + a1.z) + (a2.z + a3.z);
    acc.w = (a0.w + a1.w) + (a2.w + a3.w);

    // Fused message dropout (threefry hidden under gather latency).
    const float MSCALE = (float)(1.0 / (1.0 - 0.1));
    const uint32_t THRESH = 0xCCCCDu;
    uint32_t f = r * 64u + (uint32_t)hl * 4u;
    uint32_t b0 = tf_bits32(mk0, mk1, f + 0u);
    uint32_t b1 = tf_bits32(mk0, mk1, f + 1u);
    uint32_t b2 = tf_bits32(mk0, mk1, f + 2u);
    uint32_t b3 = tf_bits32(mk0, mk1, f + 3u);
    acc.x = ((b0 >> 9) >= THRESH) ? acc.x * MSCALE : 0.0f;
    acc.y = ((b1 >> 9) >= THRESH) ? acc.y * MSCALE : 0.0f;
    acc.z = ((b2 >> 9) >= THRESH) ? acc.z * MSCALE : 0.0f;
    acc.w = ((b3 >> 9) >= THRESH) ? acc.w * MSCALE : 0.0f;

    float4* dst = (float4*)(out + (size_t)r * ROW_STRIDE + (size_t)HOP * EMB) + hl;
    *dst = acc;
}

extern "C" void kernel_launch(void* const* d_in, const int* in_sizes, int n_in,
                              void* d_out, int out_size)
{
    const float* user_e = (const float*)d_in[0];
    const float* item_e = (const float*)d_in[1];
    const float* vals   = (const float*)d_in[2];
    const int*   rows   = (const int*)d_in[3];
    const int*   cols   = (const int*)d_in[4];
    float* out = (float*)d_out;

    // drop_key = jax.random.key(42) -> (0, 42); subkey_h = threefry(key, (0, h_data))
    uint32_t ek[3][2], mk[3][2];
    for (int h = 0; h < 3; h++) {
        threefry2x32(0u, 42u, 0u, (uint32_t)(2 * h),     ek[h][0], ek[h][1]);
        threefry2x32(0u, 42u, 0u, (uint32_t)(2 * h + 1), mk[h][0], mk[h][1]);
    }

    // Zero the packed per-row counters (graph-capturable, no allocation)
    void* cnt_ptr = nullptr;
    cudaGetSymbolAddress(&cnt_ptr, g_pcnt);
    cudaMemsetAsync(cnt_ptr, 0, sizeof(uint32_t) * N_NODES, 0);

    build_kernel<<<BUILD_BLOCKS, 256>>>(
        vals, rows, cols,
        ek[0][0], ek[0][1], ek[1][0], ek[1][1], ek[2][0], ek[2][1]);

    hop_kernel<0><<<HOP_BLOCKS, 256>>>(user_e, item_e, out, mk[0][0], mk[0][1]);
    hop_kernel<1><<<HOP_BLOCKS, 256>>>(user_e, item_e, out, mk[1][0], mk[1][1]);
    hop_kernel<2><<<HOP_BLOCKS, 256>>>(user_e, item_e, out, mk[2][0], mk[2][1]);
}

// round 8
// speedup vs baseline: 1.6391x; 1.2993x over previous
#include <cuda_runtime.h>
#include <cstdint>

#define N_USERS 100000
#define N_ITEMS 200000
#define N_NODES (N_USERS + N_ITEMS)
#define EMB 64
#define N_HOPS 3
#define NNZ 2000000
#define CAPK 24                            // max KEPT edges per row per hop (lambda ~3.35)
#define ROW_STRIDE (N_HOPS * EMB)          // 192 floats per node in output

#define BUILD_BLOCKS ((NNZ + 255) / 256)
#define HOP_BLOCKS   ((N_NODES * 16) / 256)

// Per-hop compact kept-edge lists: {v (f32 bits), col} per record.
__device__ int2     g_edge[N_HOPS][(size_t)N_NODES * CAPK];  // 3 * 57.6 MB
__device__ uint32_t g_pcnt[N_NODES];       // 3 packed 10-bit per-hop counters

__host__ __device__ __forceinline__ uint32_t rotl32(uint32_t x, int r) {
    return (x << r) | (x >> (32 - r));
}

// Threefry-2x32, 20 rounds, exactly as jax._src.prng.threefry2x32.
__host__ __device__ __forceinline__ void threefry2x32(
    uint32_t k0, uint32_t k1, uint32_t c0, uint32_t c1,
    uint32_t& o0, uint32_t& o1)
{
    uint32_t ks2 = k0 ^ k1 ^ 0x1BD11BDAu;
    uint32_t x0 = c0 + k0;
    uint32_t x1 = c1 + k1;
#define TF_ROUND(r) { x0 += x1; x1 = rotl32(x1, (r)); x1 ^= x0; }
    TF_ROUND(13) TF_ROUND(15) TF_ROUND(26) TF_ROUND(6)
    x0 += k1;  x1 += ks2 + 1u;
    TF_ROUND(17) TF_ROUND(29) TF_ROUND(16) TF_ROUND(24)
    x0 += ks2; x1 += k0 + 2u;
    TF_ROUND(13) TF_ROUND(15) TF_ROUND(26) TF_ROUND(6)
    x0 += k0;  x1 += k1 + 3u;
    TF_ROUND(17) TF_ROUND(29) TF_ROUND(16) TF_ROUND(24)
    x0 += k1;  x1 += ks2 + 4u;
    TF_ROUND(13) TF_ROUND(15) TF_ROUND(26) TF_ROUND(6)
    x0 += ks2; x1 += k0 + 5u;
#undef TF_ROUND
    o0 = x0;
    o1 = x1;
}

// jax threefry_partitionable=True, bit_width=32:
// bits[i] = w0 ^ w1 of threefry(key, (hi32(i)=0, lo32(i)=i))
__device__ __forceinline__ uint32_t tf_bits32(uint32_t k0, uint32_t k1, uint32_t i) {
    uint32_t o0, o1;
    threefry2x32(k0, k1, 0u, i, o0, o1);
    return o0 ^ o1;
}

// Build per-hop compact kept-edge lists; ONE atomic per edge (packed counters).
// edge keep = floor(0.5 + u) > 0  <=>  u >= 0.5  <=>  top bit of bits set.
__global__ void __launch_bounds__(256)
build_kernel(const float* __restrict__ vals,
             const int* __restrict__ rows,
             const int* __restrict__ cols,
             uint32_t e0k0, uint32_t e0k1,
             uint32_t e1k0, uint32_t e1k1,
             uint32_t e2k0, uint32_t e2k1)
{
    unsigned e = blockIdx.x * 256u + threadIdx.x;
    if (e >= NNZ) return;
    int r = rows[e];
    int c = cols[e];
    float v2 = vals[e] * 2.0f;            // 1/(1-0.5) rescale
    int2 rec = make_int2(__float_as_int(v2), c);

    uint32_t keep0 = tf_bits32(e0k0, e0k1, e) >> 31;
    uint32_t keep1 = tf_bits32(e1k0, e1k1, e) >> 31;
    uint32_t keep2 = tf_bits32(e2k0, e2k1, e) >> 31;
    uint32_t add = keep0 | (keep1 << 10) | (keep2 << 20);
    if (add == 0) return;

    uint32_t old = atomicAdd(&g_pcnt[r], add);
    if (keep0) {
        uint32_t s = old & 0x3FFu;
        if (s < CAPK) g_edge[0][(size_t)r * CAPK + s] = rec;
    }
    if (keep1) {
        uint32_t s = (old >> 10) & 0x3FFu;
        if (s < CAPK) g_edge[1][(size_t)r * CAPK + s] = rec;
    }
    if (keep2) {
        uint32_t s = (old >> 20) & 0x3FFu;
        if (s < CAPK) g_edge[2][(size_t)r * CAPK + s] = rec;
    }
}

// Fused SpMM + message dropout, one half-warp (16 lanes) per output row.
// Software-pipelined: slots 0/1 records + their gathers are issued
// SPECULATIVELY (stale records still hold in-range node ids, so the loads are
// always safe), in parallel with the deg load; the mdrop threefry executes
// while those loads are in flight; FFMAs are predicated on deg.
// mdrop keep = u >= 0.1f  <=>  (bits >> 9) >= 0xCCCCD  (exact on k*2^-23 grid)
template <int HOP>
__global__ void __launch_bounds__(256)
hop_kernel(const float* __restrict__ user_e,
           const float* __restrict__ item_e,
           float* __restrict__ out,
           uint32_t mk0, uint32_t mk1)
{
    unsigned t = blockIdx.x * 256u + threadIdx.x;
    unsigned r = t >> 4;                  // row = half-warp id
    int hl = t & 15;

    const int2* ebase = g_edge[HOP] + (size_t)r * CAPK;

    auto src_row = [&](int c) -> const float4* {
        if (HOP == 0) {
            return (c < N_USERS)
                ? (const float4*)(user_e + (size_t)c * EMB)
                : (const float4*)(item_e + (size_t)(c - N_USERS) * EMB);
        } else {
            return (const float4*)(out + (size_t)c * ROW_STRIDE + (size_t)(HOP - 1) * EMB);
        }
    };

    // --- issue phase: everything below is independent load traffic ---
    int2 rec0 = __ldg(&ebase[0]);          // speculative
    int2 rec1 = __ldg(&ebase[1]);          // speculative
    uint32_t pc = g_pcnt[r];
    float4 s0 = __ldg(src_row(rec0.y) + hl);   // speculative gather
    float4 s1 = __ldg(src_row(rec1.y) + hl);   // speculative gather

    // --- threefry while loads are in flight (fully independent ALU) ---
    const float MSCALE = (float)(1.0 / (1.0 - 0.1));
    const uint32_t THRESH = 0xCCCCDu;
    uint32_t f = r * 64u + (uint32_t)hl * 4u;
    uint32_t b0 = tf_bits32(mk0, mk1, f + 0u);
    uint32_t b1 = tf_bits32(mk0, mk1, f + 1u);
    uint32_t b2 = tf_bits32(mk0, mk1, f + 2u);
    uint32_t b3 = tf_bits32(mk0, mk1, f + 3u);
    float m0 = ((b0 >> 9) >= THRESH) ? MSCALE : 0.0f;
    float m1 = ((b1 >> 9) >= THRESH) ? MSCALE : 0.0f;
    float m2 = ((b2 >> 9) >= THRESH) ? MSCALE : 0.0f;
    float m3 = ((b3 >> 9) >= THRESH) ? MSCALE : 0.0f;

    int deg = (int)((pc >> (10 * HOP)) & 0x3FFu);
    if (deg > CAPK) deg = CAPK;

    // --- predicated accumulation of the speculative batch ---
    float4 a0 = make_float4(0.f, 0.f, 0.f, 0.f);
    float4 a1 = make_float4(0.f, 0.f, 0.f, 0.f);
    if (deg > 0) {
        float v = __int_as_float(rec0.x);
        a0.x = v * s0.x; a0.y = v * s0.y; a0.z = v * s0.z; a0.w = v * s0.w;
    }
    if (deg > 1) {
        float v = __int_as_float(rec1.x);
        a1.x = v * s1.x; a1.y = v * s1.y; a1.z = v * s1.z; a1.w = v * s1.w;
    }

    // --- remaining edges (27% of rows), batch-2 for MLP=2 ---
    for (int j = 2; j < deg; j += 2) {
        int2 r0 = __ldg(&ebase[j]);
        bool two = (j + 1 < deg);
        int2 r1 = two ? __ldg(&ebase[j + 1]) : make_int2(0, 0);
        float4 t0 = __ldg(src_row(r0.y) + hl);
        float v0 = __int_as_float(r0.x);
        a0.x += v0 * t0.x; a0.y += v0 * t0.y;
        a0.z += v0 * t0.z; a0.w += v0 * t0.w;
        if (two) {
            float4 t1 = __ldg(src_row(r1.y) + hl);
            float v1 = __int_as_float(r1.x);
            a1.x += v1 * t1.x; a1.y += v1 * t1.y;
            a1.z += v1 * t1.z; a1.w += v1 * t1.w;
        }
    }

    float4 acc;
    acc.x = (a0.x + a1.x) * m0;
    acc.y = (a0.y + a1.y) * m1;
    acc.z = (a0.z + a1.z) * m2;
    acc.w = (a0.w + a1.w) * m3;

    float4* dst = (float4*)(out + (size_t)r * ROW_STRIDE + (size_t)HOP * EMB) + hl;
    *dst = acc;
}

extern "C" void kernel_launch(void* const* d_in, const int* in_sizes, int n_in,
                              void* d_out, int out_size)
{
    const float* user_e = (const float*)d_in[0];
    const float* item_e = (const float*)d_in[1];
    const float* vals   = (const float*)d_in[2];
    const int*   rows   = (const int*)d_in[3];
    const int*   cols   = (const int*)d_in[4];
    float* out = (float*)d_out;

    // drop_key = jax.random.key(42) -> (0, 42); subkey_h = threefry(key, (0, h_data))
    uint32_t ek[3][2], mk[3][2];
    for (int h = 0; h < 3; h++) {
        threefry2x32(0u, 42u, 0u, (uint32_t)(2 * h),     ek[h][0], ek[h][1]);
        threefry2x32(0u, 42u, 0u, (uint32_t)(2 * h + 1), mk[h][0], mk[h][1]);
    }

    // Zero the packed per-row counters (graph-capturable, no allocation)
    void* cnt_ptr = nullptr;
    cudaGetSymbolAddress(&cnt_ptr, g_pcnt);
    cudaMemsetAsync(cnt_ptr, 0, sizeof(uint32_t) * N_NODES, 0);

    build_kernel<<<BUILD_BLOCKS, 256>>>(
        vals, rows, cols,
        ek[0][0], ek[0][1], ek[1][0], ek[1][1], ek[2][0], ek[2][1]);

    hop_kernel<0><<<HOP_BLOCKS, 256>>>(user_e, item_e, out, mk[0][0], mk[0][1]);
    hop_kernel<1><<<HOP_BLOCKS, 256>>>(user_e, item_e, out, mk[1][0], mk[1][1]);
    hop_kernel<2><<<HOP_BLOCKS, 256>>>(user_e, item_e, out, mk[2][0], mk[2][1]);
}

// round 9
// speedup vs baseline: 1.6731x; 1.0207x over previous
#include <cuda_runtime.h>
#include <cstdint>

#define N_USERS 100000
#define N_ITEMS 200000
#define N_NODES (N_USERS + N_ITEMS)
#define EMB 64
#define N_HOPS 3
#define NNZ 2000000
#define CAPK 24                            // max KEPT edges per row per hop (lambda ~3.35)
#define ROW_STRIDE (N_HOPS * EMB)          // 192 floats per node in output

#define BUILD_BLOCKS ((NNZ + 255) / 256)
#define HOP_BLOCKS   ((N_NODES * 16) / 256)

// Per-hop compact kept-edge lists: {v (f32 bits), col} per record.
// +4 records of tail padding: the 4-wide unconditional loop may read up to
// 2 records past the last row's CAPK slots.
__device__ int2     g_edge[N_HOPS][(size_t)N_NODES * CAPK + 4];  // ~3 * 57.6 MB
__device__ uint32_t g_pcnt[N_NODES];       // 3 packed 10-bit per-hop counters

__host__ __device__ __forceinline__ uint32_t rotl32(uint32_t x, int r) {
    return (x << r) | (x >> (32 - r));
}

// Threefry-2x32, 20 rounds, exactly as jax._src.prng.threefry2x32.
__host__ __device__ __forceinline__ void threefry2x32(
    uint32_t k0, uint32_t k1, uint32_t c0, uint32_t c1,
    uint32_t& o0, uint32_t& o1)
{
    uint32_t ks2 = k0 ^ k1 ^ 0x1BD11BDAu;
    uint32_t x0 = c0 + k0;
    uint32_t x1 = c1 + k1;
#define TF_ROUND(r) { x0 += x1; x1 = rotl32(x1, (r)); x1 ^= x0; }
    TF_ROUND(13) TF_ROUND(15) TF_ROUND(26) TF_ROUND(6)
    x0 += k1;  x1 += ks2 + 1u;
    TF_ROUND(17) TF_ROUND(29) TF_ROUND(16) TF_ROUND(24)
    x0 += ks2; x1 += k0 + 2u;
    TF_ROUND(13) TF_ROUND(15) TF_ROUND(26) TF_ROUND(6)
    x0 += k0;  x1 += k1 + 3u;
    TF_ROUND(17) TF_ROUND(29) TF_ROUND(16) TF_ROUND(24)
    x0 += k1;  x1 += ks2 + 4u;
    TF_ROUND(13) TF_ROUND(15) TF_ROUND(26) TF_ROUND(6)
    x0 += ks2; x1 += k0 + 5u;
#undef TF_ROUND
    o0 = x0;
    o1 = x1;
}

// jax threefry_partitionable=True, bit_width=32:
// bits[i] = w0 ^ w1 of threefry(key, (hi32(i)=0, lo32(i)=i))
__device__ __forceinline__ uint32_t tf_bits32(uint32_t k0, uint32_t k1, uint32_t i) {
    uint32_t o0, o1;
    threefry2x32(k0, k1, 0u, i, o0, o1);
    return o0 ^ o1;
}

// Build per-hop compact kept-edge lists; ONE atomic per edge (packed counters).
// edge keep = floor(0.5 + u) > 0  <=>  u >= 0.5  <=>  top bit of bits set.
__global__ void __launch_bounds__(256)
build_kernel(const float* __restrict__ vals,
             const int* __restrict__ rows,
             const int* __restrict__ cols,
             uint32_t e0k0, uint32_t e0k1,
             uint32_t e1k0, uint32_t e1k1,
             uint32_t e2k0, uint32_t e2k1)
{
    unsigned e = blockIdx.x * 256u + threadIdx.x;
    if (e >= NNZ) return;
    int r = rows[e];
    int c = cols[e];
    float v2 = vals[e] * 2.0f;            // 1/(1-0.5) rescale
    int2 rec = make_int2(__float_as_int(v2), c);

    uint32_t keep0 = tf_bits32(e0k0, e0k1, e) >> 31;
    uint32_t keep1 = tf_bits32(e1k0, e1k1, e) >> 31;
    uint32_t keep2 = tf_bits32(e2k0, e2k1, e) >> 31;
    uint32_t add = keep0 | (keep1 << 10) | (keep2 << 20);
    if (add == 0) return;

    uint32_t old = atomicAdd(&g_pcnt[r], add);
    if (keep0) {
        uint32_t s = old & 0x3FFu;
        if (s < CAPK) g_edge[0][(size_t)r * CAPK + s] = rec;
    }
    if (keep1) {
        uint32_t s = (old >> 10) & 0x3FFu;
        if (s < CAPK) g_edge[1][(size_t)r * CAPK + s] = rec;
    }
    if (keep2) {
        uint32_t s = (old >> 20) & 0x3FFu;
        if (s < CAPK) g_edge[2][(size_t)r * CAPK + s] = rec;
    }
}

// Fused SpMM + message dropout, one half-warp (16 lanes) per output row.
// Fully speculative, branch-light: record loads and gathers are issued
// unconditionally (stale/zero records hold valid finite data and in-range
// node ids, the run is deterministic), and out-of-degree contributions are
// cancelled by selecting v=0. The mdrop threefry executes while the head
// loads are in flight.
// mdrop keep = u >= 0.1f  <=>  bits >= (0xCCCCD << 9) = 0x19999A00
template <int HOP>
__global__ void __launch_bounds__(256)
hop_kernel(const float* __restrict__ user_e,
           const float* __restrict__ item_e,
           float* __restrict__ out,
           uint32_t mk0, uint32_t mk1)
{
    unsigned t = blockIdx.x * 256u + threadIdx.x;
    unsigned r = t >> 4;                  // row = half-warp id
    int hl = t & 15;

    const int2* ebase = g_edge[HOP] + (size_t)r * CAPK;

    auto src_row = [&](int c) -> const float4* {
        if (HOP == 0) {
            return (c < N_USERS)
                ? (const float4*)(user_e + (size_t)c * EMB)
                : (const float4*)(item_e + (size_t)(c - N_USERS) * EMB);
        } else {
            return (const float4*)(out + (size_t)c * ROW_STRIDE + (size_t)(HOP - 1) * EMB);
        }
    };

    // --- issue phase: independent load traffic ---
    int2 rec0 = __ldg(&ebase[0]);          // speculative
    int2 rec1 = __ldg(&ebase[1]);          // speculative
    uint32_t pc = g_pcnt[r];
    float4 s0 = __ldg(src_row(rec0.y) + hl);   // speculative gather
    float4 s1 = __ldg(src_row(rec1.y) + hl);   // speculative gather

    // --- threefry while loads are in flight (fully independent ALU) ---
    const float MSCALE = (float)(1.0 / (1.0 - 0.1));
    uint32_t f = r * 64u + (uint32_t)hl * 4u;
    uint32_t b0 = tf_bits32(mk0, mk1, f + 0u);
    uint32_t b1 = tf_bits32(mk0, mk1, f + 1u);
    uint32_t b2 = tf_bits32(mk0, mk1, f + 2u);
    uint32_t b3 = tf_bits32(mk0, mk1, f + 3u);
    float m0 = (b0 >= 0x19999A00u) ? MSCALE : 0.0f;
    float m1 = (b1 >= 0x19999A00u) ? MSCALE : 0.0f;
    float m2 = (b2 >= 0x19999A00u) ? MSCALE : 0.0f;
    float m3 = (b3 >= 0x19999A00u) ? MSCALE : 0.0f;

    int deg = (int)((pc >> (10 * HOP)) & 0x3FFu);
    if (deg > CAPK) deg = CAPK;

    // --- branchless accumulation of the speculative head ---
    float v0h = (deg > 0) ? __int_as_float(rec0.x) : 0.0f;
    float v1h = (deg > 1) ? __int_as_float(rec1.x) : 0.0f;
    float4 a0, a1;
    a0.x = v0h * s0.x; a0.y = v0h * s0.y; a0.z = v0h * s0.z; a0.w = v0h * s0.w;
    a1.x = v1h * s1.x; a1.y = v1h * s1.y; a1.z = v1h * s1.z; a1.w = v1h * s1.w;

    // --- remaining edges: 4-wide unconditional loads + gathers, MLP=4 ---
    for (int j = 2; j < deg; j += 4) {
        int2 r0 = __ldg(&ebase[j + 0]);
        int2 r1 = __ldg(&ebase[j + 1]);
        int2 r2 = __ldg(&ebase[j + 2]);
        int2 r3 = __ldg(&ebase[j + 3]);
        float4 t0 = __ldg(src_row(r0.y) + hl);
        float4 t1 = __ldg(src_row(r1.y) + hl);
        float4 t2 = __ldg(src_row(r2.y) + hl);
        float4 t3 = __ldg(src_row(r3.y) + hl);
        float v0 = (j + 0 < deg) ? __int_as_float(r0.x) : 0.0f;
        float v1 = (j + 1 < deg) ? __int_as_float(r1.x) : 0.0f;
        float v2 = (j + 2 < deg) ? __int_as_float(r2.x) : 0.0f;
        float v3 = (j + 3 < deg) ? __int_as_float(r3.x) : 0.0f;
        a0.x += v0 * t0.x; a0.y += v0 * t0.y; a0.z += v0 * t0.z; a0.w += v0 * t0.w;
        a1.x += v1 * t1.x; a1.y += v1 * t1.y; a1.z += v1 * t1.z; a1.w += v1 * t1.w;
        a0.x += v2 * t2.x; a0.y += v2 * t2.y; a0.z += v2 * t2.z; a0.w += v2 * t2.w;
        a1.x += v3 * t3.x; a1.y += v3 * t3.y; a1.z += v3 * t3.z; a1.w += v3 * t3.w;
    }

    float4 acc;
    acc.x = (a0.x + a1.x) * m0;
    acc.y = (a0.y + a1.y) * m1;
    acc.z = (a0.z + a1.z) * m2;
    acc.w = (a0.w + a1.w) * m3;

    float4* dst = (float4*)(out + (size_t)r * ROW_STRIDE + (size_t)HOP * EMB) + hl;
    *dst = acc;
}

extern "C" void kernel_launch(void* const* d_in, const int* in_sizes, int n_in,
                              void* d_out, int out_size)
{
    const float* user_e = (const float*)d_in[0];
    const float* item_e = (const float*)d_in[1];
    const float* vals   = (const float*)d_in[2];
    const int*   rows   = (const int*)d_in[3];
    const int*   cols   = (const int*)d_in[4];
    float* out = (float*)d_out;

    // drop_key = jax.random.key(42) -> (0, 42); subkey_h = threefry(key, (0, h_data))
    uint32_t ek[3][2], mk[3][2];
    for (int h = 0; h < 3; h++) {
        threefry2x32(0u, 42u, 0u, (uint32_t)(2 * h),     ek[h][0], ek[h][1]);
        threefry2x32(0u, 42u, 0u, (uint32_t)(2 * h + 1), mk[h][0], mk[h][1]);
    }

    // Zero the packed per-row counters (graph-capturable, no allocation)
    void* cnt_ptr = nullptr;
    cudaGetSymbolAddress(&cnt_ptr, g_pcnt);
    cudaMemsetAsync(cnt_ptr, 0, sizeof(uint32_t) * N_NODES, 0);

    build_kernel<<<BUILD_BLOCKS, 256>>>(
        vals, rows, cols,
        ek[0][0], ek[0][1], ek[1][0], ek[1][1], ek[2][0], ek[2][1]);

    hop_kernel<0><<<HOP_BLOCKS, 256>>>(user_e, item_e, out, mk[0][0], mk[0][1]);
    hop_kernel<1><<<HOP_BLOCKS, 256>>>(user_e, item_e, out, mk[1][0], mk[1][1]);
    hop_kernel<2><<<HOP_BLOCKS, 256>>>(user_e, item_e, out, mk[2][0], mk[2][1]);
}